// round 10
// baseline (speedup 1.0000x reference)
#include <cuda_runtime.h>
#include <cuda_fp16.h>
#include <cstdint>

#define N_NODES 50000
#define N_EDGES 800000
#define N_RELS  200
#define D       128
#define D4      (D/4)

#define SCAN_T   1024
#define N_CHUNKS ((N_NODES + SCAN_T - 1) / SCAN_T)   // 49

// Scratch (allocation-free rule: __device__ globals)
__device__ float  g_hn[N_NODES * D];    // h * norm (fp32, GEMM A-operand)
__device__ __half g_hnh[N_NODES * D];   // fp16 mirror for gather (half traffic)
__device__ __half g_rh[N_RELS * D];     // fp16 mirror of r
__device__ float  g_agg[N_NODES * D];   // norm * segment_sum(hn[src]-r[rel], dst)
__device__ int    g_cnt[N_NODES];       // per-dst degree (INVARIANT: zero at entry)
__device__ int    g_off[N_NODES + 1];   // CSR offsets
__device__ int    g_cur[N_NODES];       // running fill cursors
__device__ int    g_ekey[N_EDGES];      // packed (src<<8)|rel, bucketed by dst
__device__ int    g_bsum[64];           // per-chunk sums

// ---------------------------------------------------------------------------
// tf32 helpers (baseline PTX, no 'a' features)
// ---------------------------------------------------------------------------
__device__ __forceinline__ uint32_t f2tf32(float f) {
    uint32_t t;
    asm("cvt.rna.tf32.f32 %0, %1;" : "=r"(t) : "f"(f));
    return t;
}
__device__ __forceinline__ void mma_tf32(float* c, const uint32_t* a, const uint32_t* b) {
    asm volatile(
        "mma.sync.aligned.m16n8k8.row.col.f32.tf32.tf32.f32 "
        "{%0,%1,%2,%3}, {%4,%5,%6,%7}, {%8,%9}, {%0,%1,%2,%3};"
        : "+f"(c[0]), "+f"(c[1]), "+f"(c[2]), "+f"(c[3])
        : "r"(a[0]), "r"(a[1]), "r"(a[2]), "r"(a[3]), "r"(b[0]), "r"(b[1]));
}

__device__ __forceinline__ uint32_t pack_h2(float a, float b) {
    __half2 h = __floats2half2_rn(a, b);
    return *reinterpret_cast<uint32_t*>(&h);
}

// ---------------------------------------------------------------------------
// Kernel 1 (fused): hn = h * norm (fp32 + fp16 mirror); r -> fp16; dst histogram.
// g_cnt is zero on entry (static zero-init at load; k_scan1 resets each run).
// ---------------------------------------------------------------------------
#define PREP_T (N_NODES * D4 / 2)   // 800,000 threads

__global__ void k_prep_hist(const float* __restrict__ h,
                            const float* __restrict__ norm,
                            const int*   __restrict__ dst,
                            const float* __restrict__ r) {
    int i = blockIdx.x * blockDim.x + threadIdx.x;
    if (i >= PREP_T) return;
    atomicAdd(&g_cnt[__ldg(dst + i)], 1);    // PREP_T == N_EDGES

    if (i < N_RELS * D4) {
        float4 rv = __ldg(reinterpret_cast<const float4*>(r) + i);
        uint2 u;
        u.x = pack_h2(rv.x, rv.y);
        u.y = pack_h2(rv.z, rv.w);
        reinterpret_cast<uint2*>(g_rh)[i] = u;
    }

    const float4* h4 = reinterpret_cast<const float4*>(h);
    float4* o4 = reinterpret_cast<float4*>(g_hn);
    uint2*  o2 = reinterpret_cast<uint2*>(g_hnh);
    int j0 = i, j1 = i + PREP_T;
    float4 v0 = h4[j0];
    float4 v1 = h4[j1];
    float n0 = __ldg(norm + j0 / D4);
    float n1 = __ldg(norm + j1 / D4);
    v0.x *= n0; v0.y *= n0; v0.z *= n0; v0.w *= n0;
    v1.x *= n1; v1.y *= n1; v1.z *= n1; v1.w *= n1;
    o4[j0] = v0;
    o4[j1] = v1;
    uint2 u0, u1;
    u0.x = pack_h2(v0.x, v0.y); u0.y = pack_h2(v0.z, v0.w);
    u1.x = pack_h2(v1.x, v1.y); u1.y = pack_h2(v1.z, v1.w);
    o2[j0] = u0;
    o2[j1] = u1;
}

// ---------------------------------------------------------------------------
// Kernel 2a: per-chunk scan (coalesced). Resets g_cnt.
// ---------------------------------------------------------------------------
__global__ __launch_bounds__(SCAN_T, 1)
void k_scan1() {
    __shared__ int s[SCAN_T];
    int tid = threadIdx.x;
    int idx = blockIdx.x * SCAN_T + tid;
    int v = (idx < N_NODES) ? g_cnt[idx] : 0;
    if (idx < N_NODES) g_cnt[idx] = 0;
    s[tid] = v;
    __syncthreads();
    #pragma unroll
    for (int ofs = 1; ofs < SCAN_T; ofs <<= 1) {
        int t = (tid >= ofs) ? s[tid - ofs] : 0;
        __syncthreads();
        s[tid] += t;
        __syncthreads();
    }
    if (idx < N_NODES) g_off[idx] = s[tid] - v;
    if (tid == SCAN_T - 1) g_bsum[blockIdx.x] = s[tid];
}

// ---------------------------------------------------------------------------
// Kernel 2b: add chunk prefix, write offsets + cursors.
// ---------------------------------------------------------------------------
__global__ __launch_bounds__(SCAN_T, 1)
void k_scan2() {
    __shared__ int sb[64];
    int tid = threadIdx.x;
    if (tid < N_CHUNKS) sb[tid] = g_bsum[tid];
    __syncthreads();
    int prefix = 0;
    for (int i = 0; i < blockIdx.x; i++) prefix += sb[i];
    int idx = blockIdx.x * SCAN_T + tid;
    if (idx < N_NODES) {
        int o = g_off[idx] + prefix;
        g_off[idx] = o;
        g_cur[idx] = o;
    }
    if (idx == 0) g_off[N_NODES] = N_EDGES;
}

// ---------------------------------------------------------------------------
// Kernel 3: CSR fill — 2 edges per thread (best measured config).
// ---------------------------------------------------------------------------
__global__ void k_fill(const int* __restrict__ src,
                       const int* __restrict__ dst,
                       const int* __restrict__ rel) {
    int t = blockIdx.x * blockDim.x + threadIdx.x;
    int e0 = t * 2, e1 = t * 2 + 1;
    if (e0 >= N_EDGES) return;
    int d0 = __ldg(dst + e0);
    int k0 = (__ldg(src + e0) << 8) | __ldg(rel + e0);
    int d1 = __ldg(dst + e1);
    int k1 = (__ldg(src + e1) << 8) | __ldg(rel + e1);
    int p0 = atomicAdd(&g_cur[d0], 1);
    int p1 = atomicAdd(&g_cur[d1], 1);
    g_ekey[p0] = k0;
    g_ekey[p1] = k1;
}

// ---------------------------------------------------------------------------
// Kernel 4: gather — one warp per dst node, fp16 operands, fp32 accumulation.
// Latency-chain fix: keys prefetched COALESCED (lane l reads key e0+l, one
// 128B request per 32 edges), broadcast via shfl; hn loads issued 8-deep.
// ---------------------------------------------------------------------------
__device__ __forceinline__ void acc_edge(float4& acc, uint2 u, uint2 w) {
    __half2 d0 = __hsub2(*reinterpret_cast<__half2*>(&u.x),
                         *reinterpret_cast<__half2*>(&w.x));
    __half2 d1 = __hsub2(*reinterpret_cast<__half2*>(&u.y),
                         *reinterpret_cast<__half2*>(&w.y));
    float2 f0 = __half22float2(d0);
    float2 f1 = __half22float2(d1);
    acc.x += f0.x; acc.y += f0.y; acc.z += f1.x; acc.w += f1.y;
}

__global__ void k_gather(const float* __restrict__ norm) {
    int warp = (blockIdx.x * blockDim.x + threadIdx.x) >> 5;
    int lane = threadIdx.x & 31;
    if (warp >= N_NODES) return;

    int e0 = __ldg(g_off + warp);
    int e1 = __ldg(g_off + warp + 1);

    const uint2* hh = reinterpret_cast<const uint2*>(g_hnh);  // row stride 32
    const uint2* rr = reinterpret_cast<const uint2*>(g_rh);

    float4 acc0 = make_float4(0.f, 0.f, 0.f, 0.f);
    float4 acc1 = make_float4(0.f, 0.f, 0.f, 0.f);

    for (int base = e0; base < e1; base += 32) {
        int n = min(32, e1 - base);
        int key = 0;
        if (base + lane < e1) key = __ldg(g_ekey + base + lane);   // coalesced

        int j = 0;
        for (; j + 8 <= n; j += 8) {
            uint2 u[8], w[8];
            #pragma unroll
            for (int t = 0; t < 8; t++) {
                int k = __shfl_sync(0xffffffffu, key, j + t);
                u[t] = __ldcg(hh + (k >> 8) * 32 + lane);
                w[t] = __ldg(rr + (k & 255) * 32 + lane);
            }
            #pragma unroll
            for (int t = 0; t < 8; t++) {
                if (t & 1) acc_edge(acc1, u[t], w[t]);
                else       acc_edge(acc0, u[t], w[t]);
            }
        }
        // remainder (<8), still latency-overlapped in pairs
        for (; j + 2 <= n; j += 2) {
            int ka = __shfl_sync(0xffffffffu, key, j);
            int kb = __shfl_sync(0xffffffffu, key, j + 1);
            uint2 ua = __ldcg(hh + (ka >> 8) * 32 + lane);
            uint2 ub = __ldcg(hh + (kb >> 8) * 32 + lane);
            uint2 wa = __ldg(rr + (ka & 255) * 32 + lane);
            uint2 wb = __ldg(rr + (kb & 255) * 32 + lane);
            acc_edge(acc0, ua, wa);
            acc_edge(acc1, ub, wb);
        }
        if (j < n) {
            int k = __shfl_sync(0xffffffffu, key, j);
            uint2 u = __ldcg(hh + (k >> 8) * 32 + lane);
            uint2 w = __ldg(rr + (k & 255) * 32 + lane);
            acc_edge(acc0, u, w);
        }
    }

    float nm = __ldg(norm + warp);
    float4 o;
    o.x = (acc0.x + acc1.x) * nm;
    o.y = (acc0.y + acc1.y) * nm;
    o.z = (acc0.z + acc1.z) * nm;
    o.w = (acc0.w + acc1.w) * nm;
    reinterpret_cast<float4*>(g_agg)[warp * D4 + lane] = o;
}

// ---------------------------------------------------------------------------
// Kernel 5: tf32 mma.sync GEMM  out = relu( [hn | agg] @ [W ; W_msg] + b )
// Block tile 128x128, 8 warps; warp = 32 rows x 64 cols (2 m16 x 8 n8, k8).
// ---------------------------------------------------------------------------
#define LDB 136
#define LDA 36
#define SB_WORDS (256 * LDB)
#define SA_WORDS (128 * LDA)
#define SMEM_TC  ((SB_WORDS + 2 * SA_WORDS) * 4)   // 176,128 bytes

__global__ __launch_bounds__(256, 1)
void k_gemm_tc(const float* __restrict__ W,
               const float* __restrict__ W_msg,
               const float* __restrict__ bias,
               float* __restrict__ out) {
    extern __shared__ uint32_t smw[];
    uint32_t* sB = smw;                 // [256][LDB]
    uint32_t* sA = smw + SB_WORDS;      // 2 x [128][LDA]

    const int tid = threadIdx.x;
    const int wid = tid >> 5;
    const int lane = tid & 31;
    const int g  = lane >> 2;
    const int tg = lane & 3;
    const int tileBase = blockIdx.x * 128;
    const int wrb = (wid & 3) * 32;
    const int wcb = (wid >> 2) * 64;

    {
        #pragma unroll
        for (int i = tid; i < 256 * 32; i += 256) {
            int k = i >> 5, f4 = i & 31;
            const float4* srcp = (k < 128)
                ? reinterpret_cast<const float4*>(W) + k * 32 + f4
                : reinterpret_cast<const float4*>(W_msg) + (k - 128) * 32 + f4;
            float4 v = __ldg(srcp);
            uint4 t;
            t.x = f2tf32(v.x); t.y = f2tf32(v.y);
            t.z = f2tf32(v.z); t.w = f2tf32(v.w);
            *reinterpret_cast<uint4*>(sB + k * LDB + f4 * 4) = t;
        }
    }

    auto loadA = [&](int c, uint32_t* buf) {
        const float4* src = reinterpret_cast<const float4*>((c < 4) ? g_hn : g_agg);
        int kc = (c & 3) * 8;
        #pragma unroll
        for (int i = tid; i < 128 * 8; i += 256) {
            int row = i >> 3, f4 = i & 7;
            int gr = tileBase + row;
            float4 v = make_float4(0.f, 0.f, 0.f, 0.f);
            if (gr < N_NODES) v = __ldcg(src + gr * 32 + kc + f4);
            uint4 t;
            t.x = f2tf32(v.x); t.y = f2tf32(v.y);
            t.z = f2tf32(v.z); t.w = f2tf32(v.w);
            *reinterpret_cast<uint4*>(buf + row * LDA + f4 * 4) = t;
        }
    };

    float acc[2][8][4];
    #pragma unroll
    for (int mt = 0; mt < 2; mt++)
        #pragma unroll
        for (int nt = 0; nt < 8; nt++)
            #pragma unroll
            for (int cc = 0; cc < 4; cc++) acc[mt][nt][cc] = 0.f;

    loadA(0, sA);
    __syncthreads();

    #pragma unroll
    for (int c = 0; c < 8; c++) {
        if (c + 1 < 8) loadA(c + 1, sA + ((c + 1) & 1) * SA_WORDS);
        const uint32_t* A = sA + (c & 1) * SA_WORDS;
        const uint32_t* Bc = sB + c * 32 * LDB;

        #pragma unroll
        for (int ks = 0; ks < 4; ks++) {
            int k0 = ks * 8;
            uint32_t afr[2][4];
            #pragma unroll
            for (int mt = 0; mt < 2; mt++) {
                int rb = wrb + mt * 16 + g;
                afr[mt][0] = A[rb * LDA + k0 + tg];
                afr[mt][1] = A[(rb + 8) * LDA + k0 + tg];
                afr[mt][2] = A[rb * LDA + k0 + tg + 4];
                afr[mt][3] = A[(rb + 8) * LDA + k0 + tg + 4];
            }
            #pragma unroll
            for (int nt = 0; nt < 8; nt++) {
                uint32_t bfr[2];
                int ncol = wcb + nt * 8 + g;
                bfr[0] = Bc[(k0 + tg) * LDB + ncol];
                bfr[1] = Bc[(k0 + tg + 4) * LDB + ncol];
                mma_tf32(acc[0][nt], afr[0], bfr);
                mma_tf32(acc[1][nt], afr[1], bfr);
            }
        }
        __syncthreads();
    }

    #pragma unroll
    for (int mt = 0; mt < 2; mt++) {
        int r0 = tileBase + wrb + mt * 16 + g;
        int r1 = r0 + 8;
        #pragma unroll
        for (int nt = 0; nt < 8; nt++) {
            int col = wcb + nt * 8 + tg * 2;
            float2 bb = *reinterpret_cast<const float2*>(bias + col);
            if (r0 < N_NODES) {
                float2 o;
                o.x = fmaxf(acc[mt][nt][0] + bb.x, 0.f);
                o.y = fmaxf(acc[mt][nt][1] + bb.y, 0.f);
                *reinterpret_cast<float2*>(out + r0 * D + col) = o;
            }
            if (r1 < N_NODES) {
                float2 o;
                o.x = fmaxf(acc[mt][nt][2] + bb.x, 0.f);
                o.y = fmaxf(acc[mt][nt][3] + bb.y, 0.f);
                *reinterpret_cast<float2*>(out + r1 * D + col) = o;
            }
        }
    }
}

// ---------------------------------------------------------------------------
extern "C" void kernel_launch(void* const* d_in, const int* in_sizes, int n_in,
                              void* d_out, int out_size) {
    const float* h     = (const float*)d_in[0];
    const float* r     = (const float*)d_in[1];
    const float* norm  = (const float*)d_in[2];
    const int*   src   = (const int*)d_in[3];
    const int*   dst   = (const int*)d_in[4];
    const int*   rel   = (const int*)d_in[5];
    const float* W_msg = (const float*)d_in[6];
    const float* W     = (const float*)d_in[7];
    const float* b     = (const float*)d_in[8];
    float* out = (float*)d_out;

    // fused prep: hn (fp32 + fp16 mirror), r fp16 mirror, dst histogram
    k_prep_hist<<<(PREP_T + 255) / 256, 256>>>(h, norm, dst, r);

    // coalesced two-phase scan
    k_scan1<<<N_CHUNKS, SCAN_T>>>();
    k_scan2<<<N_CHUNKS, SCAN_T>>>();

    // CSR fill (2 edges/thread)
    k_fill<<<(N_EDGES / 2 + 255) / 256, 256>>>(src, dst, rel);

    // gather (one warp per node, coalesced key prefetch + shfl broadcast)
    k_gather<<<(N_NODES * 32 + 255) / 256, 256>>>(norm);

    // tf32 mma.sync GEMM + epilogue
    cudaFuncSetAttribute(k_gemm_tc, cudaFuncAttributeMaxDynamicSharedMemorySize, SMEM_TC);
    k_gemm_tc<<<(N_NODES + 127) / 128, 256, SMEM_TC>>>(W, W_msg, b, out);
}

// round 11
// speedup vs baseline: 1.0041x; 1.0041x over previous
#include <cuda_runtime.h>
#include <cuda_fp16.h>
#include <cstdint>

#define N_NODES 50000
#define N_EDGES 800000
#define N_RELS  200
#define D       128
#define D4      (D/4)

#define SCAN_T   1024
#define N_CHUNKS ((N_NODES + SCAN_T - 1) / SCAN_T)   // 49

// Scratch (allocation-free rule: __device__ globals)
__device__ float  g_hn[N_NODES * D];    // h * norm (fp32, GEMM A-operand)
__device__ __half g_hnh[N_NODES * D];   // fp16 mirror for gather (half traffic)
__device__ __half g_rh[N_RELS * D];     // fp16 mirror of r
__device__ float  g_agg[N_NODES * D];   // norm * segment_sum(hn[src]-r[rel], dst)
__device__ int    g_cnt[N_NODES];       // per-dst degree (INVARIANT: zero at entry)
__device__ int    g_off[N_NODES + 1];   // CSR offsets
__device__ int    g_cur[N_NODES];       // running fill cursors
__device__ int    g_ekey[N_EDGES];      // packed (src<<8)|rel, bucketed by dst
__device__ int    g_bsum[64];           // per-chunk sums

// ---------------------------------------------------------------------------
// tf32 helpers (baseline PTX, no 'a' features)
// ---------------------------------------------------------------------------
__device__ __forceinline__ uint32_t f2tf32(float f) {
    uint32_t t;
    asm("cvt.rna.tf32.f32 %0, %1;" : "=r"(t) : "f"(f));
    return t;
}
__device__ __forceinline__ void mma_tf32(float* c, const uint32_t* a, const uint32_t* b) {
    asm volatile(
        "mma.sync.aligned.m16n8k8.row.col.f32.tf32.tf32.f32 "
        "{%0,%1,%2,%3}, {%4,%5,%6,%7}, {%8,%9}, {%0,%1,%2,%3};"
        : "+f"(c[0]), "+f"(c[1]), "+f"(c[2]), "+f"(c[3])
        : "r"(a[0]), "r"(a[1]), "r"(a[2]), "r"(a[3]), "r"(b[0]), "r"(b[1]));
}

__device__ __forceinline__ uint32_t pack_h2(float a, float b) {
    __half2 h = __floats2half2_rn(a, b);
    return *reinterpret_cast<uint32_t*>(&h);
}

// ---------------------------------------------------------------------------
// Kernel 1 (fused): hn = h * norm (fp32 + fp16 mirror); r -> fp16; dst histogram.
// g_cnt is zero on entry (static zero-init at load; k_scan1 resets each run).
// ---------------------------------------------------------------------------
#define PREP_T (N_NODES * D4 / 2)   // 800,000 threads

__global__ void k_prep_hist(const float* __restrict__ h,
                            const float* __restrict__ norm,
                            const int*   __restrict__ dst,
                            const float* __restrict__ r) {
    int i = blockIdx.x * blockDim.x + threadIdx.x;
    if (i >= PREP_T) return;
    atomicAdd(&g_cnt[__ldg(dst + i)], 1);    // PREP_T == N_EDGES

    if (i < N_RELS * D4) {
        float4 rv = __ldg(reinterpret_cast<const float4*>(r) + i);
        uint2 u;
        u.x = pack_h2(rv.x, rv.y);
        u.y = pack_h2(rv.z, rv.w);
        reinterpret_cast<uint2*>(g_rh)[i] = u;
    }

    const float4* h4 = reinterpret_cast<const float4*>(h);
    float4* o4 = reinterpret_cast<float4*>(g_hn);
    uint2*  o2 = reinterpret_cast<uint2*>(g_hnh);
    int j0 = i, j1 = i + PREP_T;
    float4 v0 = h4[j0];
    float4 v1 = h4[j1];
    float n0 = __ldg(norm + j0 / D4);
    float n1 = __ldg(norm + j1 / D4);
    v0.x *= n0; v0.y *= n0; v0.z *= n0; v0.w *= n0;
    v1.x *= n1; v1.y *= n1; v1.z *= n1; v1.w *= n1;
    o4[j0] = v0;
    o4[j1] = v1;
    uint2 u0, u1;
    u0.x = pack_h2(v0.x, v0.y); u0.y = pack_h2(v0.z, v0.w);
    u1.x = pack_h2(v1.x, v1.y); u1.y = pack_h2(v1.z, v1.w);
    o2[j0] = u0;
    o2[j1] = u1;
}

// ---------------------------------------------------------------------------
// Kernel 2a: per-chunk scan (coalesced). Resets g_cnt.
// ---------------------------------------------------------------------------
__global__ __launch_bounds__(SCAN_T, 1)
void k_scan1() {
    __shared__ int s[SCAN_T];
    int tid = threadIdx.x;
    int idx = blockIdx.x * SCAN_T + tid;
    int v = (idx < N_NODES) ? g_cnt[idx] : 0;
    if (idx < N_NODES) g_cnt[idx] = 0;
    s[tid] = v;
    __syncthreads();
    #pragma unroll
    for (int ofs = 1; ofs < SCAN_T; ofs <<= 1) {
        int t = (tid >= ofs) ? s[tid - ofs] : 0;
        __syncthreads();
        s[tid] += t;
        __syncthreads();
    }
    if (idx < N_NODES) g_off[idx] = s[tid] - v;
    if (tid == SCAN_T - 1) g_bsum[blockIdx.x] = s[tid];
}

// ---------------------------------------------------------------------------
// Kernel 2b: add chunk prefix, write offsets + cursors.
// ---------------------------------------------------------------------------
__global__ __launch_bounds__(SCAN_T, 1)
void k_scan2() {
    __shared__ int sb[64];
    int tid = threadIdx.x;
    if (tid < N_CHUNKS) sb[tid] = g_bsum[tid];
    __syncthreads();
    int prefix = 0;
    for (int i = 0; i < blockIdx.x; i++) prefix += sb[i];
    int idx = blockIdx.x * SCAN_T + tid;
    if (idx < N_NODES) {
        int o = g_off[idx] + prefix;
        g_off[idx] = o;
        g_cur[idx] = o;
    }
    if (idx == 0) g_off[N_NODES] = N_EDGES;
}

// ---------------------------------------------------------------------------
// Kernel 3: CSR fill — 2 edges per thread (best measured config).
// ---------------------------------------------------------------------------
__global__ void k_fill(const int* __restrict__ src,
                       const int* __restrict__ dst,
                       const int* __restrict__ rel) {
    int t = blockIdx.x * blockDim.x + threadIdx.x;
    int e0 = t * 2, e1 = t * 2 + 1;
    if (e0 >= N_EDGES) return;
    int d0 = __ldg(dst + e0);
    int k0 = (__ldg(src + e0) << 8) | __ldg(rel + e0);
    int d1 = __ldg(dst + e1);
    int k1 = (__ldg(src + e1) << 8) | __ldg(rel + e1);
    int p0 = atomicAdd(&g_cur[d0], 1);
    int p1 = atomicAdd(&g_cur[d1], 1);
    g_ekey[p0] = k0;
    g_ekey[p1] = k1;
}

// ---------------------------------------------------------------------------
// Kernel 4: gather — one warp per dst node, fp16 operands, fp32 accumulation.
// Latency-chain fix: keys prefetched COALESCED (lane l reads key e0+l, one
// 128B request per 32 edges), broadcast via shfl; hn loads issued 8-deep.
// ---------------------------------------------------------------------------
__device__ __forceinline__ void acc_edge(float4& acc, uint2 u, uint2 w) {
    __half2 d0 = __hsub2(*reinterpret_cast<__half2*>(&u.x),
                         *reinterpret_cast<__half2*>(&w.x));
    __half2 d1 = __hsub2(*reinterpret_cast<__half2*>(&u.y),
                         *reinterpret_cast<__half2*>(&w.y));
    float2 f0 = __half22float2(d0);
    float2 f1 = __half22float2(d1);
    acc.x += f0.x; acc.y += f0.y; acc.z += f1.x; acc.w += f1.y;
}

__global__ void k_gather(const float* __restrict__ norm) {
    int warp = (blockIdx.x * blockDim.x + threadIdx.x) >> 5;
    int lane = threadIdx.x & 31;
    if (warp >= N_NODES) return;

    int e0 = __ldg(g_off + warp);
    int e1 = __ldg(g_off + warp + 1);

    const uint2* hh = reinterpret_cast<const uint2*>(g_hnh);  // row stride 32
    const uint2* rr = reinterpret_cast<const uint2*>(g_rh);

    float4 acc0 = make_float4(0.f, 0.f, 0.f, 0.f);
    float4 acc1 = make_float4(0.f, 0.f, 0.f, 0.f);

    for (int base = e0; base < e1; base += 32) {
        int n = min(32, e1 - base);
        int key = 0;
        if (base + lane < e1) key = __ldg(g_ekey + base + lane);   // coalesced

        int j = 0;
        for (; j + 8 <= n; j += 8) {
            uint2 u[8], w[8];
            #pragma unroll
            for (int t = 0; t < 8; t++) {
                int k = __shfl_sync(0xffffffffu, key, j + t);
                u[t] = __ldcg(hh + (k >> 8) * 32 + lane);
                w[t] = __ldg(rr + (k & 255) * 32 + lane);
            }
            #pragma unroll
            for (int t = 0; t < 8; t++) {
                if (t & 1) acc_edge(acc1, u[t], w[t]);
                else       acc_edge(acc0, u[t], w[t]);
            }
        }
        // remainder (<8), still latency-overlapped in pairs
        for (; j + 2 <= n; j += 2) {
            int ka = __shfl_sync(0xffffffffu, key, j);
            int kb = __shfl_sync(0xffffffffu, key, j + 1);
            uint2 ua = __ldcg(hh + (ka >> 8) * 32 + lane);
            uint2 ub = __ldcg(hh + (kb >> 8) * 32 + lane);
            uint2 wa = __ldg(rr + (ka & 255) * 32 + lane);
            uint2 wb = __ldg(rr + (kb & 255) * 32 + lane);
            acc_edge(acc0, ua, wa);
            acc_edge(acc1, ub, wb);
        }
        if (j < n) {
            int k = __shfl_sync(0xffffffffu, key, j);
            uint2 u = __ldcg(hh + (k >> 8) * 32 + lane);
            uint2 w = __ldg(rr + (k & 255) * 32 + lane);
            acc_edge(acc0, u, w);
        }
    }

    float nm = __ldg(norm + warp);
    float4 o;
    o.x = (acc0.x + acc1.x) * nm;
    o.y = (acc0.y + acc1.y) * nm;
    o.z = (acc0.z + acc1.z) * nm;
    o.w = (acc0.w + acc1.w) * nm;
    reinterpret_cast<float4*>(g_agg)[warp * D4 + lane] = o;
}

// ---------------------------------------------------------------------------
// Kernel 5: tf32 mma.sync GEMM  out = relu( [hn | agg] @ [W ; W_msg] + b )
// Block tile 128x128, 8 warps; warp = 32 rows x 64 cols (2 m16 x 8 n8, k8).
// ---------------------------------------------------------------------------
#define LDB 136
#define LDA 36
#define SB_WORDS (256 * LDB)
#define SA_WORDS (128 * LDA)
#define SMEM_TC  ((SB_WORDS + 2 * SA_WORDS) * 4)   // 176,128 bytes

__global__ __launch_bounds__(256, 1)
void k_gemm_tc(const float* __restrict__ W,
               const float* __restrict__ W_msg,
               const float* __restrict__ bias,
               float* __restrict__ out) {
    extern __shared__ uint32_t smw[];
    uint32_t* sB = smw;                 // [256][LDB]
    uint32_t* sA = smw + SB_WORDS;      // 2 x [128][LDA]

    const int tid = threadIdx.x;
    const int wid = tid >> 5;
    const int lane = tid & 31;
    const int g  = lane >> 2;
    const int tg = lane & 3;
    const int tileBase = blockIdx.x * 128;
    const int wrb = (wid & 3) * 32;
    const int wcb = (wid >> 2) * 64;

    {
        #pragma unroll
        for (int i = tid; i < 256 * 32; i += 256) {
            int k = i >> 5, f4 = i & 31;
            const float4* srcp = (k < 128)
                ? reinterpret_cast<const float4*>(W) + k * 32 + f4
                : reinterpret_cast<const float4*>(W_msg) + (k - 128) * 32 + f4;
            float4 v = __ldg(srcp);
            uint4 t;
            t.x = f2tf32(v.x); t.y = f2tf32(v.y);
            t.z = f2tf32(v.z); t.w = f2tf32(v.w);
            *reinterpret_cast<uint4*>(sB + k * LDB + f4 * 4) = t;
        }
    }

    auto loadA = [&](int c, uint32_t* buf) {
        const float4* src = reinterpret_cast<const float4*>((c < 4) ? g_hn : g_agg);
        int kc = (c & 3) * 8;
        #pragma unroll
        for (int i = tid; i < 128 * 8; i += 256) {
            int row = i >> 3, f4 = i & 7;
            int gr = tileBase + row;
            float4 v = make_float4(0.f, 0.f, 0.f, 0.f);
            if (gr < N_NODES) v = __ldcg(src + gr * 32 + kc + f4);
            uint4 t;
            t.x = f2tf32(v.x); t.y = f2tf32(v.y);
            t.z = f2tf32(v.z); t.w = f2tf32(v.w);
            *reinterpret_cast<uint4*>(buf + row * LDA + f4 * 4) = t;
        }
    };

    float acc[2][8][4];
    #pragma unroll
    for (int mt = 0; mt < 2; mt++)
        #pragma unroll
        for (int nt = 0; nt < 8; nt++)
            #pragma unroll
            for (int cc = 0; cc < 4; cc++) acc[mt][nt][cc] = 0.f;

    loadA(0, sA);
    __syncthreads();

    #pragma unroll
    for (int c = 0; c < 8; c++) {
        if (c + 1 < 8) loadA(c + 1, sA + ((c + 1) & 1) * SA_WORDS);
        const uint32_t* A = sA + (c & 1) * SA_WORDS;
        const uint32_t* Bc = sB + c * 32 * LDB;

        #pragma unroll
        for (int ks = 0; ks < 4; ks++) {
            int k0 = ks * 8;
            uint32_t afr[2][4];
            #pragma unroll
            for (int mt = 0; mt < 2; mt++) {
                int rb = wrb + mt * 16 + g;
                afr[mt][0] = A[rb * LDA + k0 + tg];
                afr[mt][1] = A[(rb + 8) * LDA + k0 + tg];
                afr[mt][2] = A[rb * LDA + k0 + tg + 4];
                afr[mt][3] = A[(rb + 8) * LDA + k0 + tg + 4];
            }
            #pragma unroll
            for (int nt = 0; nt < 8; nt++) {
                uint32_t bfr[2];
                int ncol = wcb + nt * 8 + g;
                bfr[0] = Bc[(k0 + tg) * LDB + ncol];
                bfr[1] = Bc[(k0 + tg + 4) * LDB + ncol];
                mma_tf32(acc[0][nt], afr[0], bfr);
                mma_tf32(acc[1][nt], afr[1], bfr);
            }
        }
        __syncthreads();
    }

    #pragma unroll
    for (int mt = 0; mt < 2; mt++) {
        int r0 = tileBase + wrb + mt * 16 + g;
        int r1 = r0 + 8;
        #pragma unroll
        for (int nt = 0; nt < 8; nt++) {
            int col = wcb + nt * 8 + tg * 2;
            float2 bb = *reinterpret_cast<const float2*>(bias + col);
            if (r0 < N_NODES) {
                float2 o;
                o.x = fmaxf(acc[mt][nt][0] + bb.x, 0.f);
                o.y = fmaxf(acc[mt][nt][1] + bb.y, 0.f);
                *reinterpret_cast<float2*>(out + r0 * D + col) = o;
            }
            if (r1 < N_NODES) {
                float2 o;
                o.x = fmaxf(acc[mt][nt][2] + bb.x, 0.f);
                o.y = fmaxf(acc[mt][nt][3] + bb.y, 0.f);
                *reinterpret_cast<float2*>(out + r1 * D + col) = o;
            }
        }
    }
}

// ---------------------------------------------------------------------------
extern "C" void kernel_launch(void* const* d_in, const int* in_sizes, int n_in,
                              void* d_out, int out_size) {
    const float* h     = (const float*)d_in[0];
    const float* r     = (const float*)d_in[1];
    const float* norm  = (const float*)d_in[2];
    const int*   src   = (const int*)d_in[3];
    const int*   dst   = (const int*)d_in[4];
    const int*   rel   = (const int*)d_in[5];
    const float* W_msg = (const float*)d_in[6];
    const float* W     = (const float*)d_in[7];
    const float* b     = (const float*)d_in[8];
    float* out = (float*)d_out;

    // fused prep: hn (fp32 + fp16 mirror), r fp16 mirror, dst histogram
    k_prep_hist<<<(PREP_T + 255) / 256, 256>>>(h, norm, dst, r);

    // coalesced two-phase scan
    k_scan1<<<N_CHUNKS, SCAN_T>>>();
    k_scan2<<<N_CHUNKS, SCAN_T>>>();

    // CSR fill (2 edges/thread)
    k_fill<<<(N_EDGES / 2 + 255) / 256, 256>>>(src, dst, rel);

    // gather (one warp per node, coalesced key prefetch + shfl broadcast)
    k_gather<<<(N_NODES * 32 + 255) / 256, 256>>>(norm);

    // tf32 mma.sync GEMM + epilogue
    cudaFuncSetAttribute(k_gemm_tc, cudaFuncAttributeMaxDynamicSharedMemorySize, SMEM_TC);
    k_gemm_tc<<<(N_NODES + 127) / 128, 256, SMEM_TC>>>(W, W_msg, b, out);
}